// round 5
// baseline (speedup 1.0000x reference)
#include <cuda_runtime.h>
#include <cuda_bf16.h>
#include <cstdint>
#include <cstddef>

// ---------------------------------------------------------------------------
// EarthAttention3D — Round 4: QKV projection fused into the attention kernel.
// Pipeline: [bias materialize] -> [fused qkv+attention per window] -> [out-proj]
// Shapes: B_=960, L=144, C=192, H=6, hd=32, nw=64, w_wins=15.
// ---------------------------------------------------------------------------

#define B_WIN   960
#define SEQ_L   144
#define DIM_C   192
#define NHEADS  6
#define HEADD   32
#define NWGRP   64
#define WWINS   15
#define QKVC    576
#define LL      (SEQ_L * SEQ_L)

#define XP      196    // xS row stride (== 4 mod 32 -> conflict-free A-frags)
#define WSTR    104    // W1 chunk stride (== 8 mod 32 -> conflict-free B-frags)
#define KC      48     // K-chunk rows per pipeline stage
#define QP      36     // q/k smem row stride
#define VP      40     // v smem row stride

__device__ float g_ctx[(size_t)B_WIN * SEQ_L * DIM_C];   // 106 MB
__device__ float g_bias[(size_t)NWGRP * NHEADS * LL];    // 31.9 MB

__device__ __forceinline__ uint32_t tf32u(float x) {
    uint32_t u;
    asm("cvt.rna.tf32.f32 %0, %1;" : "=r"(u) : "f"(x));
    return u;
}
__device__ __forceinline__ float tf32f(float x) { return __uint_as_float(tf32u(x)); }

__device__ __forceinline__ void mma_tf32(float c[4], const uint32_t a[4], const uint32_t b[2]) {
    asm volatile(
        "mma.sync.aligned.m16n8k8.row.col.f32.tf32.tf32.f32 "
        "{%0,%1,%2,%3}, {%4,%5,%6,%7}, {%8,%9}, {%0,%1,%2,%3};"
        : "+f"(c[0]), "+f"(c[1]), "+f"(c[2]), "+f"(c[3])
        : "r"(a[0]), "r"(a[1]), "r"(a[2]), "r"(a[3]), "r"(b[0]), "r"(b[1]));
}

__device__ __forceinline__ void cp16(void* smem_dst, const void* gmem_src) {
    uint32_t dst = (uint32_t)__cvta_generic_to_shared(smem_dst);
    asm volatile("cp.async.ca.shared.global [%0], [%1], 16;" :: "r"(dst), "l"(gmem_src));
}

// ---------------------------------------------------------------------------
// Bias materialization: g_bias[c][idx] = table[pos[idx]*384 + c]
// ---------------------------------------------------------------------------
__global__ __launch_bounds__(256) void bias_mat_kernel(
    const float* __restrict__ table, const int* __restrict__ pos,
    float* __restrict__ out)
{
    const int c   = blockIdx.y;
    const int idx = blockIdx.x * 256 + threadIdx.x;
    out[(size_t)c * LL + idx] = table[(size_t)pos[idx] * (NWGRP * NHEADS) + c];
}

// ---------------------------------------------------------------------------
// Fused QKV + attention. One block per window, 288 threads / 9 warps.
// Warp w owns rows [16w, 16w+16) throughout.
// ---------------------------------------------------------------------------
__global__ __launch_bounds__(288) void fused_attn_kernel(
    const float* __restrict__ x,
    const float* __restrict__ W1,
    const float* __restrict__ b1,
    const float* __restrict__ mask,
    const float* __restrict__ bias_mat,
    float*       __restrict__ ctx)
{
    const int bwin = blockIdx.x;
    const int nw   = (bwin / WWINS) % NWGRP;

    extern __shared__ float sm[];
    float* xS = sm;                            // [144][196]
    float* wB = xS + SEQ_L * XP;               // [2][48][104]
    float* qS = wB + 2 * KC * WSTR;            // [144][36]
    float* kS = qS + SEQ_L * QP;               // [144][36]
    float* vS = kS + SEQ_L * QP;               // [144][40]

    const int tid  = threadIdx.x;
    const int w    = tid >> 5;
    const int lane = tid & 31;
    const int g    = lane >> 2;
    const int tg   = lane & 3;
    const int r0   = 16 * w + g;
    const float scale = 0.17677669529663687f;

    // ---- async load of x window (144 x 192) into xS ----
    {
        const float* xw = x + (size_t)bwin * SEQ_L * DIM_C;
        #pragma unroll
        for (int i = 0; i < 24; i++) {
            int idx = tid + i * 288;               // 6912 float4 total
            int r = idx / 48, c4 = (idx % 48) * 4;
            cp16(&xS[r * XP + c4], xw + (size_t)r * DIM_C + c4);
        }
    }

    // W1 chunk loader: rows [c*KC, c*KC+KC) of W1, head-slice cols (3 spans of 32)
    auto load_w1 = [&](int buf, int h, int c) {
        const int k0 = c * KC;
        #pragma unroll
        for (int i = 0; i < 4; i++) {
            int idx = tid + i * 288;               // 1152 float4 total
            int r    = idx / 24;
            int rem  = idx % 24;
            int span = rem >> 3;
            int f4   = (rem & 7) * 4;
            cp16(&wB[(size_t)buf * KC * WSTR + r * WSTR + span * 32 + f4],
                 W1 + (size_t)(k0 + r) * QKVC + span * DIM_C + h * HEADD + f4);
        }
    };

    load_w1(0, 0, 0);
    asm volatile("cp.async.commit_group;");        // group: x + chunk0

    const float* mrow = mask + (size_t)bwin * LL;

    for (int h = 0; h < NHEADS; h++) {
        // ---- qkv = x @ W1_slice, pipelined over 4 K-chunks ----
        float acc[12][4] = {};                     // 16 rows x 96 cols (q|k|v)
        for (int c = 0; c < 4; c++) {
            const int s = h * 4 + c;
            if (s + 1 < 24) {
                load_w1((s + 1) & 1, (s + 1) >> 2, (s + 1) & 3);
                asm volatile("cp.async.commit_group;");
                asm volatile("cp.async.wait_group 1;");
            } else {
                asm volatile("cp.async.wait_group 0;");
            }
            __syncthreads();

            const float* wb = wB + (size_t)(s & 1) * KC * WSTR;
            const int kbase = c * KC;
            #pragma unroll
            for (int kk = 0; kk < KC / 8; kk++) {
                const int k = kbase + kk * 8;
                const int kw = kk * 8;
                uint32_t af[4];
                af[0] = tf32u(xS[r0 * XP + k + tg]);
                af[1] = tf32u(xS[(r0 + 8) * XP + k + tg]);
                af[2] = tf32u(xS[r0 * XP + k + tg + 4]);
                af[3] = tf32u(xS[(r0 + 8) * XP + k + tg + 4]);
                #pragma unroll
                for (int nt = 0; nt < 12; nt++) {
                    uint32_t bf[2];
                    bf[0] = tf32u(wb[(kw + tg) * WSTR + nt * 8 + g]);
                    bf[1] = tf32u(wb[(kw + tg + 4) * WSTR + nt * 8 + g]);
                    mma_tf32(acc[nt], af, bf);
                }
            }
            __syncthreads();
        }

        // ---- write q,k,v to smem (+b1, q scaled, tf32-rounded) ----
        #pragma unroll
        for (int nt = 0; nt < 4; nt++) {
            const int col = nt * 8 + 2 * tg;
            const int cq = h * HEADD + col;
            float bq0 = b1[cq],              bq1 = b1[cq + 1];
            float bk0 = b1[DIM_C + cq],      bk1 = b1[DIM_C + cq + 1];
            float bv0 = b1[2 * DIM_C + cq],  bv1 = b1[2 * DIM_C + cq + 1];
            qS[r0 * QP + col]           = tf32f((acc[nt][0] + bq0) * scale);
            qS[r0 * QP + col + 1]       = tf32f((acc[nt][1] + bq1) * scale);
            qS[(r0 + 8) * QP + col]     = tf32f((acc[nt][2] + bq0) * scale);
            qS[(r0 + 8) * QP + col + 1] = tf32f((acc[nt][3] + bq1) * scale);
            kS[r0 * QP + col]           = tf32f(acc[nt + 4][0] + bk0);
            kS[r0 * QP + col + 1]       = tf32f(acc[nt + 4][1] + bk1);
            kS[(r0 + 8) * QP + col]     = tf32f(acc[nt + 4][2] + bk0);
            kS[(r0 + 8) * QP + col + 1] = tf32f(acc[nt + 4][3] + bk1);
            vS[r0 * VP + col]           = tf32f(acc[nt + 8][0] + bv0);
            vS[r0 * VP + col + 1]       = tf32f(acc[nt + 8][1] + bv1);
            vS[(r0 + 8) * VP + col]     = tf32f(acc[nt + 8][2] + bv0);
            vS[(r0 + 8) * VP + col + 1] = tf32f(acc[nt + 8][3] + bv1);
        }
        __syncthreads();

        // ---- S = q @ k^T (register-resident band) ----
        float accS[18][4] = {};
        #pragma unroll
        for (int kk = 0; kk < 4; kk++) {
            const int k = kk * 8;
            uint32_t af[4];
            af[0] = __float_as_uint(qS[r0 * QP + k + tg]);
            af[1] = __float_as_uint(qS[(r0 + 8) * QP + k + tg]);
            af[2] = __float_as_uint(qS[r0 * QP + k + tg + 4]);
            af[3] = __float_as_uint(qS[(r0 + 8) * QP + k + tg + 4]);
            #pragma unroll
            for (int nt = 0; nt < 18; nt++) {
                const int cn = nt * 8 + g;
                uint32_t bf[2];
                bf[0] = __float_as_uint(kS[cn * QP + k + tg]);
                bf[1] = __float_as_uint(kS[cn * QP + k + tg + 4]);
                mma_tf32(accS[nt], af, bf);
            }
        }

        // ---- +bias +mask, softmax in registers ----
        const float* brow = bias_mat + (size_t)(nw * NHEADS + h) * LL;
        float mx0 = -1e30f, mx1 = -1e30f;
        #pragma unroll
        for (int nt = 0; nt < 18; nt++) {
            const int col = nt * 8 + 2 * tg;
            const int i0 = r0 * SEQ_L + col;
            const int i1 = (r0 + 8) * SEQ_L + col;
            float2 m0 = *(const float2*)(mrow + i0);
            float2 b0 = *(const float2*)(brow + i0);
            float2 m1 = *(const float2*)(mrow + i1);
            float2 b1v = *(const float2*)(brow + i1);
            accS[nt][0] += m0.x + b0.x;
            accS[nt][1] += m0.y + b0.y;
            accS[nt][2] += m1.x + b1v.x;
            accS[nt][3] += m1.y + b1v.y;
            mx0 = fmaxf(mx0, fmaxf(accS[nt][0], accS[nt][1]));
            mx1 = fmaxf(mx1, fmaxf(accS[nt][2], accS[nt][3]));
        }
        #pragma unroll
        for (int o = 1; o < 4; o <<= 1) {
            mx0 = fmaxf(mx0, __shfl_xor_sync(0xffffffffu, mx0, o));
            mx1 = fmaxf(mx1, __shfl_xor_sync(0xffffffffu, mx1, o));
        }
        float s0 = 0.f, s1 = 0.f;
        #pragma unroll
        for (int nt = 0; nt < 18; nt++) {
            float e0 = __expf(accS[nt][0] - mx0);
            float e1 = __expf(accS[nt][1] - mx0);
            float e2 = __expf(accS[nt][2] - mx1);
            float e3 = __expf(accS[nt][3] - mx1);
            accS[nt][0] = e0; accS[nt][1] = e1; accS[nt][2] = e2; accS[nt][3] = e3;
            s0 += e0 + e1; s1 += e2 + e3;
        }
        #pragma unroll
        for (int o = 1; o < 4; o <<= 1) {
            s0 += __shfl_xor_sync(0xffffffffu, s0, o);
            s1 += __shfl_xor_sync(0xffffffffu, s1, o);
        }
        const float inv0 = 1.f / s0, inv1 = 1.f / s1;
        #pragma unroll
        for (int nt = 0; nt < 18; nt++) {
            accS[nt][0] = tf32f(accS[nt][0] * inv0);
            accS[nt][1] = tf32f(accS[nt][1] * inv0);
            accS[nt][2] = tf32f(accS[nt][2] * inv1);
            accS[nt][3] = tf32f(accS[nt][3] * inv1);
        }

        // ---- P @ V: shuffle C-frag -> A-frag, mma with vS ----
        float acco[4][4] = {};
        const int src_lo = (g << 2) + (tg >> 1);
        const int src_hi = src_lo + 2;
        const bool sel   = tg & 1;
        #pragma unroll
        for (int kt = 0; kt < 18; kt++) {
            float v0 = __shfl_sync(0xffffffffu, accS[kt][0], src_lo);
            float v1 = __shfl_sync(0xffffffffu, accS[kt][1], src_lo);
            float v2 = __shfl_sync(0xffffffffu, accS[kt][2], src_lo);
            float v3 = __shfl_sync(0xffffffffu, accS[kt][3], src_lo);
            float v4 = __shfl_sync(0xffffffffu, accS[kt][0], src_hi);
            float v5 = __shfl_sync(0xffffffffu, accS[kt][1], src_hi);
            float v6 = __shfl_sync(0xffffffffu, accS[kt][2], src_hi);
            float v7 = __shfl_sync(0xffffffffu, accS[kt][3], src_hi);
            uint32_t a[4];
            a[0] = __float_as_uint(sel ? v1 : v0);
            a[1] = __float_as_uint(sel ? v3 : v2);
            a[2] = __float_as_uint(sel ? v5 : v4);
            a[3] = __float_as_uint(sel ? v7 : v6);
            const int kr = kt * 8;
            #pragma unroll
            for (int nt = 0; nt < 4; nt++) {
                uint32_t bf[2];
                bf[0] = __float_as_uint(vS[(kr + tg) * VP + nt * 8 + g]);
                bf[1] = __float_as_uint(vS[(kr + tg + 4) * VP + nt * 8 + g]);
                mma_tf32(acco[nt], a, bf);
            }
        }

        // ---- write head output to ctx ----
        {
            const size_t obase = (size_t)bwin * SEQ_L * DIM_C + h * HEADD;
            #pragma unroll
            for (int nt = 0; nt < 4; nt++) {
                const int col = nt * 8 + 2 * tg;
                *(float2*)&ctx[obase + (size_t)r0 * DIM_C + col] =
                    make_float2(acco[nt][0], acco[nt][1]);
                *(float2*)&ctx[obase + (size_t)(r0 + 8) * DIM_C + col] =
                    make_float2(acco[nt][2], acco[nt][3]);
            }
        }
    }
}

// ---------------------------------------------------------------------------
// tf32 GEMM (out-proj): C[M,N] = A[M,K] @ B[K,N] + bias[N]
// ---------------------------------------------------------------------------
__global__ __launch_bounds__(256, 3) void gemm_tf32_kernel(
    const float* __restrict__ A, const float* __restrict__ B,
    const float* __restrict__ bias, float* __restrict__ C,
    int M, int N, int K)
{
    __shared__ float As[2][128][36];
    __shared__ float Bs[2][32][72];

    const int bm   = blockIdx.y * 128;
    const int bn   = blockIdx.x * 64;
    const int tid  = threadIdx.x;
    const int w    = tid >> 5;
    const int lane = tid & 31;
    const int g    = lane >> 2;
    const int tg   = lane & 3;
    const int wm   = (w >> 1) * 32;
    const int wn   = (w & 1) * 32;

    auto load_stage = [&](int buf, int k0) {
        #pragma unroll
        for (int i = 0; i < 4; i++) {
            int idx = tid + i * 256;
            int r = idx >> 3, c = (idx & 7) * 4;
            cp16(&As[buf][r][c], A + (size_t)(bm + r) * K + k0 + c);
        }
        #pragma unroll
        for (int i = 0; i < 2; i++) {
            int idx = tid + i * 256;
            int r = idx >> 4, c = (idx & 15) * 4;
            cp16(&Bs[buf][r][c], B + (size_t)(k0 + r) * N + bn + c);
        }
        asm volatile("cp.async.commit_group;");
    };

    float acc[2][4][4] = {};
    load_stage(0, 0);
    const int nk = K >> 5;

    for (int ks = 0; ks < nk; ks++) {
        if (ks + 1 < nk) {
            load_stage((ks + 1) & 1, (ks + 1) << 5);
            asm volatile("cp.async.wait_group 1;");
        } else {
            asm volatile("cp.async.wait_group 0;");
        }
        __syncthreads();

        const int buf = ks & 1;
        #pragma unroll
        for (int kk = 0; kk < 4; kk++) {
            const int k = kk * 8;
            uint32_t af[2][4], bf[4][2];
            #pragma unroll
            for (int mt = 0; mt < 2; mt++) {
                int r0 = wm + mt * 16 + g;
                af[mt][0] = tf32u(As[buf][r0][k + tg]);
                af[mt][1] = tf32u(As[buf][r0 + 8][k + tg]);
                af[mt][2] = tf32u(As[buf][r0][k + tg + 4]);
                af[mt][3] = tf32u(As[buf][r0 + 8][k + tg + 4]);
            }
            #pragma unroll
            for (int nt = 0; nt < 4; nt++) {
                int cn = wn + nt * 8 + g;
                bf[nt][0] = tf32u(Bs[buf][k + tg][cn]);
                bf[nt][1] = tf32u(Bs[buf][k + tg + 4][cn]);
            }
            #pragma unroll
            for (int mt = 0; mt < 2; mt++)
                #pragma unroll
                for (int nt = 0; nt < 4; nt++)
                    mma_tf32(acc[mt][nt], af[mt], bf[nt]);
        }
        __syncthreads();
    }

    #pragma unroll
    for (int mt = 0; mt < 2; mt++) {
        #pragma unroll
        for (int nt = 0; nt < 4; nt++) {
            int r0  = bm + wm + mt * 16 + g;
            int col = bn + wn + nt * 8 + 2 * tg;
            float b0 = bias[col], b1 = bias[col + 1];
            *(float2*)&C[(size_t)r0 * N + col]       = make_float2(acc[mt][nt][0] + b0, acc[mt][nt][1] + b1);
            *(float2*)&C[(size_t)(r0 + 8) * N + col] = make_float2(acc[mt][nt][2] + b0, acc[mt][nt][3] + b1);
        }
    }
}

// ---------------------------------------------------------------------------
extern "C" void kernel_launch(void* const* d_in, const int* in_sizes, int n_in,
                              void* d_out, int out_size)
{
    (void)in_sizes; (void)n_in; (void)out_size;
    const float* x          = (const float*)d_in[0];
    const float* mask       = (const float*)d_in[1];
    const float* W1         = (const float*)d_in[2];
    const float* b1         = (const float*)d_in[3];
    const float* W2         = (const float*)d_in[4];
    const float* b2         = (const float*)d_in[5];
    const float* bias_table = (const float*)d_in[6];
    const int*   pos        = (const int*)d_in[7];
    float*       out        = (float*)d_out;

    float* ctx;  cudaGetSymbolAddress((void**)&ctx, g_ctx);
    float* bmat; cudaGetSymbolAddress((void**)&bmat, g_bias);

    const int M = B_WIN * SEQ_L;

    // 0) materialize earth bias
    bias_mat_kernel<<<dim3(LL / 256, NWGRP * NHEADS), 256>>>(bias_table, pos, bmat);

    // 1) fused qkv + attention (one block per window)
    const int smem_bytes =
        (SEQ_L * XP + 2 * KC * WSTR + 2 * SEQ_L * QP + SEQ_L * VP) * (int)sizeof(float); // 217344
    cudaFuncSetAttribute(fused_attn_kernel, cudaFuncAttributeMaxDynamicSharedMemorySize, smem_bytes);
    fused_attn_kernel<<<B_WIN, 288, smem_bytes>>>(x, W1, b1, mask, bmat, ctx);

    // 2) output projection
    gemm_tf32_kernel<<<dim3(DIM_C / 64, M / 128), 256>>>(ctx, W2, b2, out, M, DIM_C, DIM_C);
}